// round 2
// baseline (speedup 1.0000x reference)
#include <cuda_runtime.h>
#include <math.h>

// Problem constants
#define NB   128      // batch
#define ND   20       // depth
#define NW   8        // width
#define NIN  64       // W*W
#define NHID 4096     // W^4
#define NE   4        // experts
#define OUT_ELEMS (NB*ND*NIN)   // 163840

// Scratch (device globals; no allocations allowed)
__device__ float g_flat[NB*NIN];
__device__ int   g_expert[NB];
__device__ int   g_list[NE*NB];
__device__ int   g_count[NE];
__device__ float g_h[NB*NHID];   // 2 MB
__device__ float g_z[NB*NHID];   // 2 MB, z then softmax in place

// ---------------------------------------------------------------------------
// Kernel A: conv1(3x3x3,pad1)+relu -> conv2(20x3x3,padD0)+relu -> flat(64)
//           -> gate logits -> argmax expert. One block per sample b.
// ---------------------------------------------------------------------------
__global__ __launch_bounds__(256) void k_conv_gate(
    const float* __restrict__ input,
    const float* __restrict__ c1w, const float* __restrict__ c1b,
    const float* __restrict__ c2w, const float* __restrict__ c2b,
    const float* __restrict__ wg)
{
    int b   = blockIdx.x;
    int tid = threadIdx.x;       // 256
    int slot = tid >> 6;         // 0..3
    int pos  = tid & 63;         // 0..63
    int pi = pos >> 3, pj = pos & 7;

    __shared__ float s_plane[4][64];
    __shared__ float s_red[4][64];
    __shared__ float s_in[ND*NIN];   // cache the sample (5 KB)
    __shared__ float s_flat[64];
    __shared__ float s_log[NE];

    for (int i = tid; i < ND*NIN; i += 256)
        s_in[i] = input[b*ND*NIN + i];
    __syncthreads();

    float facc = 0.f;

    // 200 planes = (c in 0..9) x (dz in 0..19); 4 slots -> 50 per slot
    for (int plane = slot; plane < 200; plane += 4) {
        int c  = plane / 20;
        int dz = plane % 20;
        // conv1 output at (c, dz, pi, pj), padding 1 in all dims
        float a = c1b[c];
        #pragma unroll
        for (int az = 0; az < 3; az++) {
            int d = dz + az - 1;
            if ((unsigned)d < (unsigned)ND) {
                #pragma unroll
                for (int ai = 0; ai < 3; ai++) {
                    int ii = pi + ai - 1;
                    if ((unsigned)ii < 8u) {
                        #pragma unroll
                        for (int aj = 0; aj < 3; aj++) {
                            int jj = pj + aj - 1;
                            if ((unsigned)jj < 8u)
                                a += c1w[c*27 + az*9 + ai*3 + aj] *
                                     s_in[d*64 + ii*8 + jj];
                        }
                    }
                }
            }
        }
        a = fmaxf(a, 0.f);
        s_plane[slot][pos] = a;
        __syncthreads();
        // conv2 (3x3 spatial, full-D reduce): this plane's contribution
        float f = 0.f;
        #pragma unroll
        for (int di = 0; di < 3; di++) {
            int ii = pi + di - 1;
            if ((unsigned)ii < 8u) {
                #pragma unroll
                for (int dj = 0; dj < 3; dj++) {
                    int jj = pj + dj - 1;
                    if ((unsigned)jj < 8u)
                        f += c2w[plane*9 + di*3 + dj] * s_plane[slot][ii*8 + jj];
                }
            }
        }
        facc += f;
        __syncthreads();
    }

    s_red[slot][pos] = facc;
    __syncthreads();
    if (tid < 64) {
        float f = s_red[0][tid] + s_red[1][tid] + s_red[2][tid] + s_red[3][tid]
                + c2b[0];
        f = fmaxf(f, 0.f);
        s_flat[tid] = f;
        g_flat[b*64 + tid] = f;
    }
    __syncthreads();
    if (tid < NE) {
        float l = 0.f;
        #pragma unroll 8
        for (int i = 0; i < 64; i++) l += s_flat[i] * wg[i*NE + tid];
        s_log[tid] = l;
    }
    __syncthreads();
    if (tid == 0) {
        int best = 0; float bl = s_log[0];
        #pragma unroll
        for (int e = 1; e < NE; e++)
            if (s_log[e] > bl) { bl = s_log[e]; best = e; }
        g_expert[b] = best;   // top-1 gate value is exactly 1.0 (softmax of 1)
    }
}

// ---------------------------------------------------------------------------
// Kernel B: per-expert sample lists + counts + aux loss. One block, 128 thr.
// importance == load == counts (gate values are exactly 1.0), so
// aux = 2 * cv^2(counts) * 1e-2 with ddof=1 variance.
// ---------------------------------------------------------------------------
__global__ void k_assign(float* __restrict__ out, int out_size)
{
    __shared__ int s_cnt[NE];
    int tid = threadIdx.x;   // 128
    if (tid < NE) s_cnt[tid] = 0;
    __syncthreads();
    int e = g_expert[tid];
    int p = atomicAdd(&s_cnt[e], 1);
    g_list[e*NB + p] = tid;
    __syncthreads();
    if (tid < NE) g_count[tid] = s_cnt[tid];
    if (tid == 0) {
        float mean = (float)NB / (float)NE;    // 32
        float var = 0.f;
        #pragma unroll
        for (int i = 0; i < NE; i++) { float d = (float)s_cnt[i] - mean; var += d*d; }
        var /= (float)(NE - 1);
        float cv2 = var / (mean*mean + 1e-10f);
        float aux = 2.f * cv2 * 1e-2f;
        if (out_size > OUT_ELEMS) out[OUT_ELEMS] = aux;
    }
}

// ---------------------------------------------------------------------------
// Kernel C: h[s] = relu(flat[s] @ w1[e] + b1[e]) grouped by expert.
// Each thread owns one o column, keeps the 64 w1 values in registers,
// loops expert's samples from smem. w1 read exactly once (4 MB total).
// ---------------------------------------------------------------------------
__global__ __launch_bounds__(256) void k_h(
    const float* __restrict__ w1, const float* __restrict__ b1)
{
    int e = blockIdx.y;
    int cnt = g_count[e];
    if (cnt == 0) return;
    int tid = threadIdx.x;
    int o = blockIdx.x * 256 + tid;

    __shared__ float s_f[NB*NIN];   // up to 32 KB (all flats of this expert)
    for (int idx = tid; idx < cnt*64; idx += 256) {
        int m = idx >> 6, i = idx & 63;
        s_f[idx] = g_flat[g_list[e*NB + m]*64 + i];
    }
    __syncthreads();

    float w[64];
    #pragma unroll
    for (int i = 0; i < 64; i++) w[i] = w1[(size_t)(e*64 + i)*NHID + o];
    float bb = b1[e*NHID + o];

    for (int m = 0; m < cnt; m++) {
        const float* f = &s_f[m*64];
        float acc = bb;
        #pragma unroll
        for (int i = 0; i < 64; i++) acc += f[i] * w[i];
        g_h[(size_t)g_list[e*NB + m]*NHID + o] = fmaxf(acc, 0.f);
    }
}

// ---------------------------------------------------------------------------
// Kernel D (dominant): z = h @ w2[e] + b2[e], grouped by expert.
// Tile: M=32 samples (covers whole expert in balanced case -> w2 streamed
// exactly once), N=128 cols, K-chunk 32. 256 threads, 4x4 micro-tile.
// Register double-buffer: next K-chunk prefetched during compute.
// ---------------------------------------------------------------------------
#define MT 32
#define NT 128
#define KC 32

__global__ __launch_bounds__(256) void k_gemm(
    const float* __restrict__ w2, const float* __restrict__ b2)
{
    int e = blockIdx.z;
    int cnt = g_count[e];
    int m0 = blockIdx.y * MT;
    if (m0 >= cnt) return;
    int n0 = blockIdx.x * NT;
    int tid = threadIdx.x;
    int tx = tid & 31;          // 32 n-groups of 4 cols
    int ty = tid >> 5;          // 8 m-groups of 4 rows

    __shared__ float hs[KC][MT];    // [k][m]
    __shared__ float ws[KC][NT];    // [k][n]
    __shared__ int   s_list[MT];

    if (tid < MT) {
        int m = m0 + tid;
        s_list[tid] = (m < cnt) ? g_list[e*NB + m] : -1;
    }
    __syncthreads();

    const float* w2e = w2 + (size_t)e*NHID*NHID + n0;
    int wcol = tx*4;
    // h prefetch: thread loads hs[ty + r*8][tx] for r=0..3
    int hsamp = s_list[tx];
    const float* hrow = g_h + (size_t)(hsamp < 0 ? 0 : hsamp)*NHID;

    float4 wreg[4];
    float  hreg[4];

    // prologue: prefetch chunk 0
    #pragma unroll
    for (int r = 0; r < 4; r++)
        wreg[r] = *(const float4*)&w2e[(size_t)(ty + r*8)*NHID + wcol];
    #pragma unroll
    for (int r = 0; r < 4; r++)
        hreg[r] = (hsamp >= 0) ? hrow[ty + r*8] : 0.f;

    float acc[4][4] = {};

    for (int kc = 0; kc < NHID; kc += KC) {
        // regs -> smem (conflict-free: consecutive tx -> consecutive m / n)
        #pragma unroll
        for (int r = 0; r < 4; r++) *(float4*)&ws[ty + r*8][wcol] = wreg[r];
        #pragma unroll
        for (int r = 0; r < 4; r++) hs[ty + r*8][tx] = hreg[r];
        __syncthreads();

        // prefetch next chunk into registers (overlaps with compute below)
        int kn = kc + KC;
        if (kn < NHID) {
            #pragma unroll
            for (int r = 0; r < 4; r++)
                wreg[r] = *(const float4*)&w2e[(size_t)(kn + ty + r*8)*NHID + wcol];
            #pragma unroll
            for (int r = 0; r < 4; r++)
                hreg[r] = (hsamp >= 0) ? hrow[kn + ty + r*8] : 0.f;
        }

        #pragma unroll
        for (int k = 0; k < KC; k++) {
            float4 hv = *(const float4*)&hs[k][ty*4];   // broadcast within warp
            float4 wv = *(const float4*)&ws[k][tx*4];
            acc[0][0] += hv.x*wv.x; acc[0][1] += hv.x*wv.y;
            acc[0][2] += hv.x*wv.z; acc[0][3] += hv.x*wv.w;
            acc[1][0] += hv.y*wv.x; acc[1][1] += hv.y*wv.y;
            acc[1][2] += hv.y*wv.z; acc[1][3] += hv.y*wv.w;
            acc[2][0] += hv.z*wv.x; acc[2][1] += hv.z*wv.y;
            acc[2][2] += hv.z*wv.z; acc[2][3] += hv.z*wv.w;
            acc[3][0] += hv.w*wv.x; acc[3][1] += hv.w*wv.y;
            acc[3][2] += hv.w*wv.z; acc[3][3] += hv.w*wv.w;
        }
        __syncthreads();
    }

    int n = n0 + tx*4;
    float4 bv = *(const float4*)&b2[e*NHID + n];
    #pragma unroll
    for (int i = 0; i < 4; i++) {
        int s = s_list[ty*4 + i];
        if (s >= 0) {
            float4 o;
            o.x = acc[i][0] + bv.x; o.y = acc[i][1] + bv.y;
            o.z = acc[i][2] + bv.z; o.w = acc[i][3] + bv.w;
            *(float4*)&g_z[(size_t)s*NHID + n] = o;
        }
    }
}

// ---------------------------------------------------------------------------
// Kernel E: row softmax over HID=4096, in place. One block per sample.
// ---------------------------------------------------------------------------
__global__ __launch_bounds__(256) void k_softmax()
{
    int b = blockIdx.x;
    int tid = threadIdx.x;
    float* z = g_z + (size_t)b*NHID;
    __shared__ float red[256];

    float mx = -1e30f;
    for (int i = tid; i < NHID; i += 256) mx = fmaxf(mx, z[i]);
    red[tid] = mx;
    __syncthreads();
    for (int s = 128; s > 0; s >>= 1) {
        if (tid < s) red[tid] = fmaxf(red[tid], red[tid + s]);
        __syncthreads();
    }
    mx = red[0];
    __syncthreads();

    float sum = 0.f;
    for (int i = tid; i < NHID; i += 256) {
        float v = __expf(z[i] - mx);
        z[i] = v;
        sum += v;
    }
    red[tid] = sum;
    __syncthreads();
    for (int s = 128; s > 0; s >>= 1) {
        if (tid < s) red[tid] += red[tid + s];
        __syncthreads();
    }
    float inv = 1.f / red[0];
    for (int i = tid; i < NHID; i += 256) z[i] *= inv;
}

// ---------------------------------------------------------------------------
// Kernel F: out[b,d,p] = sigmoid( sum_q y[b][p*64+q] * input[b,d,q] ).
// One block per sample; y transposed into smem for conflict-free reads.
// ---------------------------------------------------------------------------
__global__ __launch_bounds__(256) void k_out(
    const float* __restrict__ input, float* __restrict__ out)
{
    int b = blockIdx.x;
    int tid = threadIdx.x;
    __shared__ float syT[NHID];     // [q][p] layout
    __shared__ float sin[ND*NIN];

    for (int j = tid; j < NHID; j += 256) {
        int q = j >> 6, p = j & 63;
        syT[j] = g_z[(size_t)b*NHID + p*64 + q];
    }
    for (int i = tid; i < ND*NIN; i += 256)
        sin[i] = input[b*ND*NIN + i];
    __syncthreads();

    for (int u = tid; u < ND*NIN; u += 256) {
        int d = u >> 6, p = u & 63;
        float acc = 0.f;
        #pragma unroll 16
        for (int q = 0; q < 64; q++)
            acc += syT[q*64 + p] * sin[d*64 + q];
        out[b*ND*NIN + u] = 1.f / (1.f + __expf(-acc));
    }
}

// ---------------------------------------------------------------------------
extern "C" void kernel_launch(void* const* d_in, const int* in_sizes, int n_in,
                              void* d_out, int out_size)
{
    const float* input = (const float*)d_in[0];
    const float* c1w   = (const float*)d_in[1];
    const float* c1b   = (const float*)d_in[2];
    const float* c2w   = (const float*)d_in[3];
    const float* c2b   = (const float*)d_in[4];
    const float* wg    = (const float*)d_in[5];
    const float* w1    = (const float*)d_in[6];
    const float* b1    = (const float*)d_in[7];
    const float* w2    = (const float*)d_in[8];
    const float* b2    = (const float*)d_in[9];
    float* out = (float*)d_out;

    k_conv_gate<<<NB, 256>>>(input, c1w, c1b, c2w, c2b, wg);
    k_assign<<<1, NB>>>(out, out_size);
    k_h<<<dim3(NHID/256, NE), 256>>>(w1, b1);
    k_gemm<<<dim3(NHID/NT, NB/MT, NE), 256>>>(w2, b2);
    k_softmax<<<NB, 256>>>();
    k_out<<<NB, 256>>>(input, out);
}

// round 3
// speedup vs baseline: 2.0629x; 2.0629x over previous
#include <cuda_runtime.h>
#include <math.h>

// Problem constants
#define NB   128      // batch
#define ND   20       // depth
#define NW   8        // width
#define NIN  64       // W*W
#define NHID 4096     // W^4
#define NE   4        // experts
#define OUT_ELEMS (NB*ND*NIN)   // 163840

#define KSPLIT 4
#define KLEN   (NHID/KSPLIT)    // 1024

// Scratch (device globals; no allocations allowed)
__device__ float g_flat[NB*NIN];
__device__ int   g_expert[NB];
__device__ int   g_list[NE*NB];
__device__ int   g_count[NE];
__device__ float g_h[NB*NHID];              // 2 MB
__device__ float g_z[NB*NHID];              // 2 MB (softmax output)
__device__ float g_zpart[KSPLIT*NB*NHID];   // 8 MB split-K partials

// ---------------------------------------------------------------------------
// Kernel A: conv1(3x3x3,pad1)+relu -> conv2(20x3x3,padD0)+relu -> flat(64)
//           -> gate logits -> argmax expert. One block per sample b.
// ---------------------------------------------------------------------------
__global__ __launch_bounds__(256) void k_conv_gate(
    const float* __restrict__ input,
    const float* __restrict__ c1w, const float* __restrict__ c1b,
    const float* __restrict__ c2w, const float* __restrict__ c2b,
    const float* __restrict__ wg)
{
    int b   = blockIdx.x;
    int tid = threadIdx.x;       // 256
    int slot = tid >> 6;         // 0..3
    int pos  = tid & 63;         // 0..63
    int pi = pos >> 3, pj = pos & 7;

    __shared__ float s_plane[4][64];
    __shared__ float s_red[4][64];
    __shared__ float s_in[ND*NIN];   // cache the sample (5 KB)
    __shared__ float s_flat[64];
    __shared__ float s_log[NE];

    for (int i = tid; i < ND*NIN; i += 256)
        s_in[i] = input[b*ND*NIN + i];
    __syncthreads();

    float facc = 0.f;

    // 200 planes = (c in 0..9) x (dz in 0..19); 4 slots -> 50 per slot
    for (int plane = slot; plane < 200; plane += 4) {
        int c  = plane / 20;
        int dz = plane % 20;
        float a = c1b[c];
        #pragma unroll
        for (int az = 0; az < 3; az++) {
            int d = dz + az - 1;
            if ((unsigned)d < (unsigned)ND) {
                #pragma unroll
                for (int ai = 0; ai < 3; ai++) {
                    int ii = pi + ai - 1;
                    if ((unsigned)ii < 8u) {
                        #pragma unroll
                        for (int aj = 0; aj < 3; aj++) {
                            int jj = pj + aj - 1;
                            if ((unsigned)jj < 8u)
                                a += c1w[c*27 + az*9 + ai*3 + aj] *
                                     s_in[d*64 + ii*8 + jj];
                        }
                    }
                }
            }
        }
        a = fmaxf(a, 0.f);
        s_plane[slot][pos] = a;
        __syncthreads();
        float f = 0.f;
        #pragma unroll
        for (int di = 0; di < 3; di++) {
            int ii = pi + di - 1;
            if ((unsigned)ii < 8u) {
                #pragma unroll
                for (int dj = 0; dj < 3; dj++) {
                    int jj = pj + dj - 1;
                    if ((unsigned)jj < 8u)
                        f += c2w[plane*9 + di*3 + dj] * s_plane[slot][ii*8 + jj];
                }
            }
        }
        facc += f;
        __syncthreads();
    }

    s_red[slot][pos] = facc;
    __syncthreads();
    if (tid < 64) {
        float f = s_red[0][tid] + s_red[1][tid] + s_red[2][tid] + s_red[3][tid]
                + c2b[0];
        f = fmaxf(f, 0.f);
        s_flat[tid] = f;
        g_flat[b*64 + tid] = f;
    }
    __syncthreads();
    if (tid < NE) {
        float l = 0.f;
        #pragma unroll 8
        for (int i = 0; i < 64; i++) l += s_flat[i] * wg[i*NE + tid];
        s_log[tid] = l;
    }
    __syncthreads();
    if (tid == 0) {
        int best = 0; float bl = s_log[0];
        #pragma unroll
        for (int e = 1; e < NE; e++)
            if (s_log[e] > bl) { bl = s_log[e]; best = e; }
        g_expert[b] = best;   // top-1 gate value is exactly 1.0 (softmax of 1)
    }
}

// ---------------------------------------------------------------------------
// Kernel B: per-expert sample lists + counts + aux loss. One block, 128 thr.
// ---------------------------------------------------------------------------
__global__ void k_assign(float* __restrict__ out, int out_size)
{
    __shared__ int s_cnt[NE];
    int tid = threadIdx.x;   // 128
    if (tid < NE) s_cnt[tid] = 0;
    __syncthreads();
    int e = g_expert[tid];
    int p = atomicAdd(&s_cnt[e], 1);
    g_list[e*NB + p] = tid;
    __syncthreads();
    if (tid < NE) g_count[tid] = s_cnt[tid];
    if (tid == 0) {
        float mean = (float)NB / (float)NE;    // 32
        float var = 0.f;
        #pragma unroll
        for (int i = 0; i < NE; i++) { float d = (float)s_cnt[i] - mean; var += d*d; }
        var /= (float)(NE - 1);
        float cv2 = var / (mean*mean + 1e-10f);
        float aux = 2.f * cv2 * 1e-2f;
        if (out_size > OUT_ELEMS) out[OUT_ELEMS] = aux;
    }
}

// ---------------------------------------------------------------------------
// Kernel C: h[s] = relu(flat[s] @ w1[e] + b1[e]) grouped by expert.
// ---------------------------------------------------------------------------
__global__ __launch_bounds__(256) void k_h(
    const float* __restrict__ w1, const float* __restrict__ b1)
{
    int e = blockIdx.y;
    int cnt = g_count[e];
    if (cnt == 0) return;
    int tid = threadIdx.x;
    int o = blockIdx.x * 256 + tid;

    __shared__ float s_f[NB*NIN];
    for (int idx = tid; idx < cnt*64; idx += 256) {
        int m = idx >> 6, i = idx & 63;
        s_f[idx] = g_flat[g_list[e*NB + m]*64 + i];
    }
    __syncthreads();

    float w[64];
    #pragma unroll
    for (int i = 0; i < 64; i++) w[i] = w1[(size_t)(e*64 + i)*NHID + o];
    float bb = b1[e*NHID + o];

    for (int m = 0; m < cnt; m++) {
        const float* f = &s_f[m*64];
        float acc = bb;
        #pragma unroll
        for (int i = 0; i < 64; i++) acc += f[i] * w[i];
        g_h[(size_t)g_list[e*NB + m]*NHID + o] = fmaxf(acc, 0.f);
    }
}

// ---------------------------------------------------------------------------
// Kernel D (dominant): split-K GEMM partials: zpart[ks] = h @ w2[e][ksK:...]
// Tile: M=32, N=128, K-chunk 32, split-K 4 -> 512 working CTAs.
// Double-buffered smem, register prefetch, ONE sync per chunk.
// ---------------------------------------------------------------------------
#define MT 32
#define NT 128
#define KC 32
#define MTP (MT+4)   // pad keeps float4 alignment (36 floats = 144B, 16B mult)

__global__ __launch_bounds__(256, 3) void k_gemm(const float* __restrict__ w2)
{
    int ez = blockIdx.z;
    int e  = ez >> 2;          // expert
    int ks = ez & 3;           // K-split index
    int cnt = g_count[e];
    int m0 = blockIdx.y * MT;
    if (m0 >= cnt) return;
    int n0 = blockIdx.x * NT;
    int tid = threadIdx.x;
    int tx = tid & 31;          // n-group (4 cols)
    int ty = tid >> 5;          // 0..7

    __shared__ float hs[2][KC][MTP];
    __shared__ float ws[2][KC][NT];
    __shared__ int   s_list[MT];

    if (tid < MT) {
        int m = m0 + tid;
        s_list[tid] = (m < cnt) ? g_list[e*NB + m] : -1;
    }
    __syncthreads();

    const float* w2e = w2 + (size_t)e*NHID*NHID + (size_t)ks*KLEN*NHID + n0;

    // h loader mapping: 8 threads per sample row, float4 each (coalesced)
    int msel = tid >> 3;            // 0..31 sample slot
    int k0   = (tid & 7) * 4;       // 0..28
    int hsamp = s_list[msel];
    const float* hrow = g_h + (size_t)(hsamp < 0 ? 0 : hsamp)*NHID + ks*KLEN;

    float4 wreg[4], hreg;

    // prefetch chunk 0
    #pragma unroll
    for (int r = 0; r < 4; r++)
        wreg[r] = *(const float4*)&w2e[(size_t)(ty + r*8)*NHID + tx*4];
    hreg = (hsamp >= 0) ? *(const float4*)&hrow[k0] : make_float4(0,0,0,0);

    // store to buffer 0
    #pragma unroll
    for (int r = 0; r < 4; r++) *(float4*)&ws[0][ty + r*8][tx*4] = wreg[r];
    hs[0][k0+0][msel] = hreg.x; hs[0][k0+1][msel] = hreg.y;
    hs[0][k0+2][msel] = hreg.z; hs[0][k0+3][msel] = hreg.w;
    __syncthreads();

    float acc[4][4] = {};
    int cur = 0;

    #pragma unroll 1
    for (int c = 0; c < KLEN/KC; c++) {
        int kn = (c + 1) * KC;
        bool more = kn < KLEN;
        if (more) {
            #pragma unroll
            for (int r = 0; r < 4; r++)
                wreg[r] = *(const float4*)&w2e[(size_t)(kn + ty + r*8)*NHID + tx*4];
            hreg = (hsamp >= 0) ? *(const float4*)&hrow[kn + k0]
                                : make_float4(0,0,0,0);
        }

        #pragma unroll
        for (int k = 0; k < KC; k++) {
            float4 hv = *(const float4*)&hs[cur][k][ty*4];   // warp broadcast
            float4 wv = *(const float4*)&ws[cur][k][tx*4];
            acc[0][0] += hv.x*wv.x; acc[0][1] += hv.x*wv.y;
            acc[0][2] += hv.x*wv.z; acc[0][3] += hv.x*wv.w;
            acc[1][0] += hv.y*wv.x; acc[1][1] += hv.y*wv.y;
            acc[1][2] += hv.y*wv.z; acc[1][3] += hv.y*wv.w;
            acc[2][0] += hv.z*wv.x; acc[2][1] += hv.z*wv.y;
            acc[2][2] += hv.z*wv.z; acc[2][3] += hv.z*wv.w;
            acc[3][0] += hv.w*wv.x; acc[3][1] += hv.w*wv.y;
            acc[3][2] += hv.w*wv.z; acc[3][3] += hv.w*wv.w;
        }

        if (more) {
            #pragma unroll
            for (int r = 0; r < 4; r++) *(float4*)&ws[cur^1][ty + r*8][tx*4] = wreg[r];
            hs[cur^1][k0+0][msel] = hreg.x; hs[cur^1][k0+1][msel] = hreg.y;
            hs[cur^1][k0+2][msel] = hreg.z; hs[cur^1][k0+3][msel] = hreg.w;
        }
        __syncthreads();
        cur ^= 1;
    }

    int n = n0 + tx*4;
    #pragma unroll
    for (int i = 0; i < 4; i++) {
        int s = s_list[ty*4 + i];
        if (s >= 0) {
            float4 o;
            o.x = acc[i][0]; o.y = acc[i][1]; o.z = acc[i][2]; o.w = acc[i][3];
            *(float4*)&g_zpart[((size_t)ks*NB + s)*NHID + n] = o;
        }
    }
}

// ---------------------------------------------------------------------------
// Kernel E: reduce split-K partials + b2, then row softmax. One block/sample.
// ---------------------------------------------------------------------------
__global__ __launch_bounds__(256) void k_softmax(const float* __restrict__ b2)
{
    int b = blockIdx.x;
    int tid = threadIdx.x;
    int e = g_expert[b];
    float* z = g_z + (size_t)b*NHID;
    const float* b2e = b2 + e*NHID;
    __shared__ float red[256];

    float mx = -1e30f;
    for (int i = tid; i < NHID; i += 256) {
        float v = b2e[i];
        #pragma unroll
        for (int ks = 0; ks < KSPLIT; ks++)
            v += g_zpart[((size_t)ks*NB + b)*NHID + i];
        z[i] = v;
        mx = fmaxf(mx, v);
    }
    red[tid] = mx;
    __syncthreads();
    for (int s = 128; s > 0; s >>= 1) {
        if (tid < s) red[tid] = fmaxf(red[tid], red[tid + s]);
        __syncthreads();
    }
    mx = red[0];
    __syncthreads();

    float sum = 0.f;
    for (int i = tid; i < NHID; i += 256) {
        float v = __expf(z[i] - mx);
        z[i] = v;
        sum += v;
    }
    red[tid] = sum;
    __syncthreads();
    for (int s = 128; s > 0; s >>= 1) {
        if (tid < s) red[tid] += red[tid + s];
        __syncthreads();
    }
    float inv = 1.f / red[0];
    for (int i = tid; i < NHID; i += 256) z[i] *= inv;
}

// ---------------------------------------------------------------------------
// Kernel F: out[b,d,p] = sigmoid( sum_q y[b][p*64+q] * input[b,d,q] ).
// ---------------------------------------------------------------------------
__global__ __launch_bounds__(256) void k_out(
    const float* __restrict__ input, float* __restrict__ out)
{
    int b = blockIdx.x;
    int tid = threadIdx.x;
    __shared__ float syT[NHID];     // [q][p] layout
    __shared__ float sin[ND*NIN];

    for (int j = tid; j < NHID; j += 256) {
        int q = j >> 6, p = j & 63;
        syT[j] = g_z[(size_t)b*NHID + p*64 + q];
    }
    for (int i = tid; i < ND*NIN; i += 256)
        sin[i] = input[b*ND*NIN + i];
    __syncthreads();

    for (int u = tid; u < ND*NIN; u += 256) {
        int d = u >> 6, p = u & 63;
        float acc = 0.f;
        #pragma unroll 16
        for (int q = 0; q < 64; q++)
            acc += syT[q*64 + p] * sin[d*64 + q];
        out[b*ND*NIN + u] = 1.f / (1.f + __expf(-acc));
    }
}

// ---------------------------------------------------------------------------
extern "C" void kernel_launch(void* const* d_in, const int* in_sizes, int n_in,
                              void* d_out, int out_size)
{
    const float* input = (const float*)d_in[0];
    const float* c1w   = (const float*)d_in[1];
    const float* c1b   = (const float*)d_in[2];
    const float* c2w   = (const float*)d_in[3];
    const float* c2b   = (const float*)d_in[4];
    const float* wg    = (const float*)d_in[5];
    const float* w1    = (const float*)d_in[6];
    const float* b1    = (const float*)d_in[7];
    const float* w2    = (const float*)d_in[8];
    const float* b2    = (const float*)d_in[9];
    float* out = (float*)d_out;

    k_conv_gate<<<NB, 256>>>(input, c1w, c1b, c2w, c2b, wg);
    k_assign<<<1, NB>>>(out, out_size);
    k_h<<<dim3(NHID/256, NE), 256>>>(w1, b1);
    k_gemm<<<dim3(NHID/NT, NB/MT, NE*KSPLIT), 256>>>(w2);
    k_softmax<<<NB, 256>>>(b2);
    k_out<<<NB, 256>>>(input, out);
}